// round 11
// baseline (speedup 1.0000x reference)
#include <cuda_runtime.h>
#include <cstdint>

#define BB 16
#define NN 1024
#define DD 128
#define BN (BB*NN)

// ---------------- packed fp32x2 helpers (sm_103a) ----------------
__device__ __forceinline__ void ffma2(uint64_t& d, uint64_t a, uint64_t b) {
    asm("fma.rn.f32x2 %0, %1, %2, %0;" : "+l"(d) : "l"(a), "l"(b));
}
__device__ __forceinline__ float2 unpack2(uint64_t p) {
    float2 v; asm("mov.b64 {%0, %1}, %2;" : "=f"(v.x), "=f"(v.y) : "l"(p)); return v;
}

// ---------------- scratch ----------------
__device__ float g_WwT[DD*DD];
__device__ float g_M  [DD*DD];               // A + A^T
__device__ float g_h  [BN*DD];
__device__ float g_g  [BN*DD];               // g = h @ (A+A^T)
__device__ float g_scores[(size_t)BB*NN*NN]; // exp'd masked numerators
__device__ float g_z  [BB*NN];
__device__ float g_hp [BN*DD];

// ---------------- K0: transpose Ww, form M = A+A^T, zero g_z ----------------
__global__ void k_prep(const float* __restrict__ Ww, const float* __restrict__ A) {
    int i = blockIdx.x * 256 + threadIdx.x;   // 16384 == DD*DD == BB*NN
    int d = i >> 7, f = i & 127;
    g_WwT[f * DD + d] = Ww[d * DD + f];
    g_M[d * DD + f] = A[d * DD + f] + A[f * DD + d];
    g_z[i] = 0.f;
}

// ---------------- K1: fused h = x@Ww^T + Wb ; g = h@M ----------------
__global__ __launch_bounds__(256) void k_h_g(const float* __restrict__ x,
                                             const float* __restrict__ Wb) {
    __shared__ float sX[64 * 128];
    int t = threadIdx.x;
    int tx = t & 31, ty = t >> 5;
    int row0 = blockIdx.x * 64;

    #pragma unroll
    for (int i = 0; i < 32; i++) {
        int idx = i * 256 + t;
        sX[idx] = x[(size_t)row0 * DD + idx];
    }
    __syncthreads();

    float acc[8][4];
    float4 wb4 = *(const float4*)&Wb[tx * 4];
    #pragma unroll
    for (int i = 0; i < 8; i++) { acc[i][0]=wb4.x; acc[i][1]=wb4.y; acc[i][2]=wb4.z; acc[i][3]=wb4.w; }
    for (int f = 0; f < 128; f++) {
        float4 w = *(const float4*)&g_WwT[f * DD + tx * 4];
        #pragma unroll
        for (int i = 0; i < 8; i++) {
            float xv = sX[(ty * 8 + i) * 128 + f];
            acc[i][0] += xv * w.x; acc[i][1] += xv * w.y;
            acc[i][2] += xv * w.z; acc[i][3] += xv * w.w;
        }
    }
    __syncthreads();
    #pragma unroll
    for (int i = 0; i < 8; i++) {
        int r = ty * 8 + i;
        float4 v; v.x = acc[i][0]; v.y = acc[i][1]; v.z = acc[i][2]; v.w = acc[i][3];
        *(float4*)&g_h[(size_t)(row0 + r) * DD + tx * 4] = v;
        *(float4*)&sX[r * 128 + tx * 4] = v;
    }
    __syncthreads();

    float acc2[8][4];
    #pragma unroll
    for (int i = 0; i < 8; i++) { acc2[i][0]=0.f; acc2[i][1]=0.f; acc2[i][2]=0.f; acc2[i][3]=0.f; }
    for (int f = 0; f < 128; f++) {
        float4 m4 = *(const float4*)&g_M[f * DD + tx * 4];
        #pragma unroll
        for (int i = 0; i < 8; i++) {
            float hv = sX[(ty * 8 + i) * 128 + f];
            acc2[i][0] += hv * m4.x; acc2[i][1] += hv * m4.y;
            acc2[i][2] += hv * m4.z; acc2[i][3] += hv * m4.w;
        }
    }
    #pragma unroll
    for (int i = 0; i < 8; i++) {
        float4 v; v.x = acc2[i][0]; v.y = acc2[i][1]; v.z = acc2[i][2]; v.w = acc2[i][3];
        *(float4*)&g_g[(size_t)(row0 + ty * 8 + i) * DD + tx * 4] = v;
    }
}

// ---------------- K3: e_sym = g @ h^T ; exp+mask+colsum fused ----------------
// a-pairs stride 34 (16B-aligned even kk) -> LDS.128 loads 2 kk's dup pairs in 1 issue.
#define SMEM_K3 (128 * 129 * 4)   // 66048 B (transpose buffer dominates the union)
__global__ __launch_bounds__(256) void k_scores(const float* __restrict__ adj) {
    extern __shared__ float sm[];
    float2* sG2 = (float2*)sm;                 // 128 x 34 float2 dup pairs = 34816 B
    float*  sHT = sm + 128 * 34 * 2;           // 32 x 130 floats = 16640 B

    int u = blockIdx.x, b = blockIdx.y;
    int tj = 0, rem = u;
    while (rem >= 8 - tj) { rem -= 8 - tj; tj++; }
    int tk = tj + rem;
    int j0 = tj * 128, k0 = tk * 128;

    int t = threadIdx.x, tx = t & 15, ty = t >> 4;
    const float* Hb = g_h + (size_t)b * NN * DD;
    const float* Gb = g_g + (size_t)b * NN * DD;

    uint64_t accp[8][4];
    #pragma unroll
    for (int i = 0; i < 8; i++)
        #pragma unroll
        for (int j = 0; j < 4; j++) accp[i][j] = 0ull;

    for (int ch = 0; ch < 4; ch++) {
        int c = t & 31, r0 = t >> 5;
        #pragma unroll
        for (int i = 0; i < 16; i++) {
            int r = r0 + 8 * i;
            float gv = Gb[(size_t)(j0 + r) * DD + ch * 32 + c];
            sG2[r * 34 + c] = make_float2(gv, gv);
            sHT[c * 130 + r] = Hb[(size_t)(k0 + r) * DD + ch * 32 + c];
        }
        __syncthreads();
        #pragma unroll 4
        for (int kk = 0; kk < 32; kk += 2) {
            uint64_t bp0[4], bp1[4];
            #pragma unroll
            for (int jj = 0; jj < 4; jj++) {
                bp0[jj] = *(const uint64_t*)&sHT[kk * 130 + jj * 32 + tx * 2];
                bp1[jj] = *(const uint64_t*)&sHT[(kk + 1) * 130 + jj * 32 + tx * 2];
            }
            #pragma unroll
            for (int i = 0; i < 8; i++) {
                ulonglong2 a2 = *(const ulonglong2*)&sG2[(ty * 8 + i) * 34 + kk];
                #pragma unroll
                for (int jj = 0; jj < 4; jj++) {
                    ffma2(accp[i][jj], a2.x, bp0[jj]);
                    ffma2(accp[i][jj], a2.y, bp1[jj]);
                }
            }
        }
        __syncthreads();
    }

    float acc[8][8];
    #pragma unroll
    for (int i = 0; i < 8; i++)
        #pragma unroll
        for (int jj = 0; jj < 4; jj++) {
            float2 v = unpack2(accp[i][jj]);
            acc[i][2 * jj] = v.x; acc[i][2 * jj + 1] = v.y;
        }

    const float* adjb = adj + (size_t)b * NN * NN;
    float* scb = g_scores + (size_t)b * NN * NN;

    float colp[8];
    #pragma unroll
    for (int jj = 0; jj < 8; jj++) colp[jj] = 0.f;

    #pragma unroll
    for (int i = 0; i < 8; i++) {
        int j = j0 + ty * 8 + i;
        #pragma unroll
        for (int jj = 0; jj < 4; jj++) {
            int k = k0 + jj * 32 + tx * 2;
            float2 am = *(const float2*)&adjb[(size_t)j * NN + k];
            float2 v;
            v.x = am.x > 0.f ? __expf(acc[i][2 * jj + 0]) : 0.f;
            v.y = am.y > 0.f ? __expf(acc[i][2 * jj + 1]) : 0.f;
            colp[2 * jj + 0] += am.x > 0.f ? v.x : 1.f;
            colp[2 * jj + 1] += am.y > 0.f ? v.y : 1.f;
            *(float2*)&scb[(size_t)j * NN + k] = v;
        }
    }

    float* sC = sm;   // 16 x 128 floats
    __syncthreads();
    #pragma unroll
    for (int jj = 0; jj < 4; jj++) {
        sC[ty * 128 + jj * 32 + tx * 2 + 0] = colp[2 * jj + 0];
        sC[ty * 128 + jj * 32 + tx * 2 + 1] = colp[2 * jj + 1];
    }
    __syncthreads();
    if (t < 128) {
        float z = 0.f;
        #pragma unroll
        for (int q = 0; q < 16; q++) z += sC[q * 128 + t];
        atomicAdd(&g_z[b * NN + k0 + t], z);
    }

    if (tj != tk) {
        __syncthreads();
        float* sT = sm;   // 128 x 129 floats
        #pragma unroll
        for (int i = 0; i < 8; i++)
            #pragma unroll
            for (int jj = 0; jj < 4; jj++) {
                sT[(jj * 32 + tx * 2 + 0) * 129 + (ty * 8 + i)] = acc[i][2 * jj + 0];
                sT[(jj * 32 + tx * 2 + 1) * 129 + (ty * 8 + i)] = acc[i][2 * jj + 1];
            }
        __syncthreads();
        int c = t & 127, r0b = t >> 7;
        float zM = 0.f;
        #pragma unroll 4
        for (int p = 0; p < 64; p++) {
            int r = r0b + 2 * p;
            int k = k0 + r, j = j0 + c;
            float am = adjb[(size_t)k * NN + j];
            float ev = am > 0.f ? __expf(sT[r * 129 + c]) : 0.f;
            zM += am > 0.f ? ev : 1.f;
            scb[(size_t)k * NN + j] = ev;
        }
        atomicAdd(&g_z[b * NN + j0 + c], zM);
    }
}

// ---------------- K5: h_prime = relu( (n / z_col) @ h ) ----------------
// 64x128 tile, 256 threads (32x8), 8x4 micro-tile, LDS.128 a-pairs (2 kk / issue).
#define SMEM_K5 (64 * 34 * 8 + 32 * 130 * 4)   // 17408 + 16640 = 34048 B
__global__ __launch_bounds__(256, 2) void k_hprime() {
    extern __shared__ float smem5[];
    float2* sA2 = (float2*)smem5;              // 64 x 34 dup pairs
    float*  sH  = smem5 + 64 * 34 * 2;         // 32 x 130
    int b = blockIdx.y, i0 = blockIdx.x * 64;
    int t = threadIdx.x, tx = t & 31, ty = t >> 5;   // 32 x 8
    const float* scb = g_scores + (size_t)b * NN * NN;
    const float* Hb  = g_h      + (size_t)b * NN * DD;
    const float* zb  = g_z      + b * NN;

    uint64_t accp[8][2];
    #pragma unroll
    for (int i = 0; i < 8; i++) { accp[i][0] = 0ull; accp[i][1] = 0ull; }

    for (int ch = 0; ch < 32; ch++) {
        int jbase = ch * 32;
        {   // attention tile 64x32 (dup pairs): a = numerator * 1/z
            int c = tx, r0 = ty;
            float rz = __fdividef(1.0f, zb[jbase + c]);
            #pragma unroll
            for (int p = 0; p < 8; p++) {
                int r = r0 + 8 * p;
                float v = scb[(size_t)(i0 + r) * NN + jbase + c] * rz;
                sA2[r * 34 + c] = make_float2(v, v);
            }
        }
        {   // h tile 32x128
            int c2 = t & 127, r0b = t >> 7;
            #pragma unroll
            for (int p = 0; p < 16; p++) {
                int r = r0b + 2 * p;
                sH[r * 130 + c2] = Hb[(size_t)(jbase + r) * DD + c2];
            }
        }
        __syncthreads();
        #pragma unroll 4
        for (int kk = 0; kk < 32; kk += 2) {
            uint64_t b00 = *(const uint64_t*)&sH[kk * 130 + tx * 2];
            uint64_t b01 = *(const uint64_t*)&sH[kk * 130 + 64 + tx * 2];
            uint64_t b10 = *(const uint64_t*)&sH[(kk + 1) * 130 + tx * 2];
            uint64_t b11 = *(const uint64_t*)&sH[(kk + 1) * 130 + 64 + tx * 2];
            #pragma unroll
            for (int i = 0; i < 8; i++) {
                ulonglong2 a2 = *(const ulonglong2*)&sA2[(ty * 8 + i) * 34 + kk];
                ffma2(accp[i][0], a2.x, b00);
                ffma2(accp[i][1], a2.x, b01);
                ffma2(accp[i][0], a2.y, b10);
                ffma2(accp[i][1], a2.y, b11);
            }
        }
        __syncthreads();
    }
    float* hpb = g_hp + (size_t)b * NN * DD;
    #pragma unroll
    for (int i = 0; i < 8; i++) {
        int row = i0 + ty * 8 + i;
        float2 v0 = unpack2(accp[i][0]);
        float2 v1 = unpack2(accp[i][1]);
        v0.x = fmaxf(v0.x, 0.f); v0.y = fmaxf(v0.y, 0.f);
        v1.x = fmaxf(v1.x, 0.f); v1.y = fmaxf(v1.y, 0.f);
        *(float2*)&hpb[(size_t)row * DD + tx * 2]      = v0;
        *(float2*)&hpb[(size_t)row * DD + 64 + tx * 2] = v1;
    }
}

// ---------------- K6: gates + output ----------------
__global__ __launch_bounds__(256) void k_out(const float* __restrict__ x,
        const float* __restrict__ wi_u, const float* __restrict__ wi_x,
        const float* __restrict__ wf_u, const float* __restrict__ wf_x,
        const float* __restrict__ wo_u, const float* __restrict__ wo_x,
        float* __restrict__ out) {
    int node = blockIdx.x * 8 + (threadIdx.x >> 5);
    int lane = threadIdx.x & 31;
    size_t base = (size_t)node * DD;
    float hp4[4], x4[4];
    float si = 0.f, sf = 0.f, so = 0.f;
    #pragma unroll
    for (int i = 0; i < 4; i++) {
        int d = lane + 32 * i;
        hp4[i] = g_hp[base + d];
        x4[i]  = x[base + d];
        si += hp4[i] * wi_u[d] + x4[i] * wi_x[d];
        sf += hp4[i] * wf_u[d] + x4[i] * wf_x[d];
        so += hp4[i] * wo_u[d] + x4[i] * wo_x[d];
    }
    #pragma unroll
    for (int off = 16; off; off >>= 1) {
        si += __shfl_xor_sync(0xffffffffu, si, off);
        sf += __shfl_xor_sync(0xffffffffu, sf, off);
        so += __shfl_xor_sync(0xffffffffu, so, off);
    }
    float ic = 1.f / (1.f + __expf(-si));
    float fc = 1.f / (1.f + __expf(-sf));
    float oc = 1.f / (1.f + __expf(-so));
    #pragma unroll
    for (int i = 0; i < 4; i++) {
        int d = lane + 32 * i;
        out[base + d] = oc * tanhf(ic * hp4[i] + fc * x4[i]);
    }
}

// ---------------- launch ----------------
extern "C" void kernel_launch(void* const* d_in, const int* in_sizes, int n_in,
                              void* d_out, int out_size) {
    const float* x    = (const float*)d_in[0];
    const float* adj  = (const float*)d_in[1];
    const float* Ww   = (const float*)d_in[2];
    const float* Wb   = (const float*)d_in[3];
    const float* A    = (const float*)d_in[4];
    const float* wi_u = (const float*)d_in[5];
    const float* wi_x = (const float*)d_in[6];
    const float* wf_u = (const float*)d_in[7];
    const float* wf_x = (const float*)d_in[8];
    const float* wo_u = (const float*)d_in[9];
    const float* wo_x = (const float*)d_in[10];
    float* out = (float*)d_out;

    cudaFuncSetAttribute(k_scores, cudaFuncAttributeMaxDynamicSharedMemorySize, SMEM_K3);
    cudaFuncSetAttribute(k_hprime, cudaFuncAttributeMaxDynamicSharedMemorySize, SMEM_K5);

    k_prep<<<64, 256>>>(Ww, A);
    k_h_g<<<BN / 64, 256>>>(x, Wb);
    k_scores<<<dim3(36, BB), 256, SMEM_K3>>>(adj);
    k_hprime<<<dim3(NN / 64, BB), 256, SMEM_K5>>>();
    k_out<<<BN / 8, 256>>>(x, wi_u, wi_x, wf_u, wf_x, wo_u, wo_x, out);
}

// round 14
// speedup vs baseline: 1.2401x; 1.2401x over previous
#include <cuda_runtime.h>
#include <cuda_bf16.h>
#include <cstdint>

#define BB 16
#define NN 1024
#define DD 128
#define BN (BB*NN)

// ---------------- packed fp32x2 helpers (sm_103a) ----------------
__device__ __forceinline__ void ffma2(uint64_t& d, uint64_t a, uint64_t b) {
    asm("fma.rn.f32x2 %0, %1, %2, %0;" : "+l"(d) : "l"(a), "l"(b));
}
__device__ __forceinline__ float2 unpack2(uint64_t p) {
    float2 v; asm("mov.b64 {%0, %1}, %2;" : "=f"(v.x), "=f"(v.y) : "l"(p)); return v;
}

// pack float -> (bf16 hi | bf16 lo<<16)
__device__ __forceinline__ uint32_t packbf(float v) {
    __nv_bfloat16 hi = __float2bfloat16(v);
    float lof = v - __bfloat162float(hi);
    __nv_bfloat16 lo = __float2bfloat16(lof);
    return (uint32_t)__bfloat16_as_ushort(hi) | ((uint32_t)__bfloat16_as_ushort(lo) << 16);
}

// mma.sync m16n8k16 row.col f32.bf16.bf16.f32 (arch-generic HMMA)
__device__ __forceinline__ void mma16816(float* d, const uint32_t* a, const uint32_t* b) {
    asm volatile(
        "mma.sync.aligned.m16n8k16.row.col.f32.bf16.bf16.f32 "
        "{%0,%1,%2,%3}, {%4,%5,%6,%7}, {%8,%9}, {%0,%1,%2,%3};"
        : "+f"(d[0]), "+f"(d[1]), "+f"(d[2]), "+f"(d[3])
        : "r"(a[0]), "r"(a[1]), "r"(a[2]), "r"(a[3]), "r"(b[0]), "r"(b[1]));
}

// ---------------- scratch ----------------
__device__ float    g_WwT[DD*DD];
__device__ float    g_M  [DD*DD];               // A + A^T
__device__ float    g_h  [BN*DD];
__device__ float    g_g  [BN*DD];               // g = h @ (A+A^T)
__device__ uint32_t g_scores[(size_t)BB*NN*NN]; // packed bf16 (hi,lo) numerators
__device__ float    g_z  [BB*NN];
__device__ uint32_t g_hbf[(size_t)BB*DD*NN];    // B' = rz[j]*h[j][d], packed, [b][d][j]
__device__ float    g_hp [BN*DD];

// ---------------- K0: transpose Ww, form M = A+A^T, zero g_z ----------------
__global__ void k_prep(const float* __restrict__ Ww, const float* __restrict__ A) {
    int i = blockIdx.x * 256 + threadIdx.x;
    int d = i >> 7, f = i & 127;
    g_WwT[f * DD + d] = Ww[d * DD + f];
    g_M[d * DD + f] = A[d * DD + f] + A[f * DD + d];
    g_z[i] = 0.f;
}

// ---------------- K1: fused h = x@Ww^T + Wb ; g = h@M ----------------
__global__ __launch_bounds__(256) void k_h_g(const float* __restrict__ x,
                                             const float* __restrict__ Wb) {
    __shared__ float sX[64 * 128];
    int t = threadIdx.x;
    int tx = t & 31, ty = t >> 5;
    int row0 = blockIdx.x * 64;

    #pragma unroll
    for (int i = 0; i < 32; i++) {
        int idx = i * 256 + t;
        sX[idx] = x[(size_t)row0 * DD + idx];
    }
    __syncthreads();

    float acc[8][4];
    float4 wb4 = *(const float4*)&Wb[tx * 4];
    #pragma unroll
    for (int i = 0; i < 8; i++) { acc[i][0]=wb4.x; acc[i][1]=wb4.y; acc[i][2]=wb4.z; acc[i][3]=wb4.w; }
    for (int f = 0; f < 128; f++) {
        float4 w = *(const float4*)&g_WwT[f * DD + tx * 4];
        #pragma unroll
        for (int i = 0; i < 8; i++) {
            float xv = sX[(ty * 8 + i) * 128 + f];
            acc[i][0] += xv * w.x; acc[i][1] += xv * w.y;
            acc[i][2] += xv * w.z; acc[i][3] += xv * w.w;
        }
    }
    __syncthreads();
    #pragma unroll
    for (int i = 0; i < 8; i++) {
        int r = ty * 8 + i;
        float4 v; v.x = acc[i][0]; v.y = acc[i][1]; v.z = acc[i][2]; v.w = acc[i][3];
        *(float4*)&g_h[(size_t)(row0 + r) * DD + tx * 4] = v;
        *(float4*)&sX[r * 128 + tx * 4] = v;
    }
    __syncthreads();

    float acc2[8][4];
    #pragma unroll
    for (int i = 0; i < 8; i++) { acc2[i][0]=0.f; acc2[i][1]=0.f; acc2[i][2]=0.f; acc2[i][3]=0.f; }
    for (int f = 0; f < 128; f++) {
        float4 m4 = *(const float4*)&g_M[f * DD + tx * 4];
        #pragma unroll
        for (int i = 0; i < 8; i++) {
            float hv = sX[(ty * 8 + i) * 128 + f];
            acc2[i][0] += hv * m4.x; acc2[i][1] += hv * m4.y;
            acc2[i][2] += hv * m4.z; acc2[i][3] += hv * m4.w;
        }
    }
    #pragma unroll
    for (int i = 0; i < 8; i++) {
        float4 v; v.x = acc2[i][0]; v.y = acc2[i][1]; v.z = acc2[i][2]; v.w = acc2[i][3];
        *(float4*)&g_g[(size_t)(row0 + ty * 8 + i) * DD + tx * 4] = v;
    }
}

// ---------------- K3: e_sym = g @ h^T ; exp+mask+colsum; writes packed bf16 pairs ----------------
#define SMEM_K3 (128 * 129 * 4)
__global__ __launch_bounds__(256) void k_scores(const float* __restrict__ adj) {
    extern __shared__ float sm[];
    float2* sG2 = (float2*)sm;                 // 128 x 33 float2 (dup pairs)
    float*  sHT = sm + 128 * 33 * 2;           // 32 x 130 floats

    int u = blockIdx.x, b = blockIdx.y;
    int tj = 0, rem = u;
    while (rem >= 8 - tj) { rem -= 8 - tj; tj++; }
    int tk = tj + rem;
    int j0 = tj * 128, k0 = tk * 128;

    int t = threadIdx.x, tx = t & 15, ty = t >> 4;
    const float* Hb = g_h + (size_t)b * NN * DD;
    const float* Gb = g_g + (size_t)b * NN * DD;

    uint64_t accp[8][4];
    #pragma unroll
    for (int i = 0; i < 8; i++)
        #pragma unroll
        for (int j = 0; j < 4; j++) accp[i][j] = 0ull;

    for (int ch = 0; ch < 4; ch++) {
        int c = t & 31, r0 = t >> 5;
        #pragma unroll
        for (int i = 0; i < 16; i++) {
            int r = r0 + 8 * i;
            float gv = Gb[(size_t)(j0 + r) * DD + ch * 32 + c];
            sG2[r * 33 + c] = make_float2(gv, gv);
            sHT[c * 130 + r] = Hb[(size_t)(k0 + r) * DD + ch * 32 + c];
        }
        __syncthreads();
        for (int kk = 0; kk < 32; kk++) {
            uint64_t bp[4];
            #pragma unroll
            for (int jj = 0; jj < 4; jj++)
                bp[jj] = *(const uint64_t*)&sHT[kk * 130 + jj * 32 + tx * 2];
            #pragma unroll
            for (int i = 0; i < 8; i++) {
                uint64_t ap = *(const uint64_t*)&sG2[(ty * 8 + i) * 33 + kk];
                #pragma unroll
                for (int jj = 0; jj < 4; jj++)
                    ffma2(accp[i][jj], ap, bp[jj]);
            }
        }
        __syncthreads();
    }

    float acc[8][8];
    #pragma unroll
    for (int i = 0; i < 8; i++)
        #pragma unroll
        for (int jj = 0; jj < 4; jj++) {
            float2 v = unpack2(accp[i][jj]);
            acc[i][2 * jj] = v.x; acc[i][2 * jj + 1] = v.y;
        }

    const float* adjb = adj + (size_t)b * NN * NN;
    uint32_t* scb = g_scores + (size_t)b * NN * NN;

    float colp[8];
    #pragma unroll
    for (int jj = 0; jj < 8; jj++) colp[jj] = 0.f;

    #pragma unroll
    for (int i = 0; i < 8; i++) {
        int j = j0 + ty * 8 + i;
        #pragma unroll
        for (int jj = 0; jj < 4; jj++) {
            int k = k0 + jj * 32 + tx * 2;
            float2 am = *(const float2*)&adjb[(size_t)j * NN + k];
            float vx = am.x > 0.f ? __expf(acc[i][2 * jj + 0]) : 0.f;
            float vy = am.y > 0.f ? __expf(acc[i][2 * jj + 1]) : 0.f;
            colp[2 * jj + 0] += am.x > 0.f ? vx : 1.f;
            colp[2 * jj + 1] += am.y > 0.f ? vy : 1.f;
            uint2 pk; pk.x = packbf(vx); pk.y = packbf(vy);
            *(uint2*)&scb[(size_t)j * NN + k] = pk;
        }
    }

    float* sC = sm;
    __syncthreads();
    #pragma unroll
    for (int jj = 0; jj < 4; jj++) {
        sC[ty * 128 + jj * 32 + tx * 2 + 0] = colp[2 * jj + 0];
        sC[ty * 128 + jj * 32 + tx * 2 + 1] = colp[2 * jj + 1];
    }
    __syncthreads();
    if (t < 128) {
        float z = 0.f;
        #pragma unroll
        for (int q = 0; q < 16; q++) z += sC[q * 128 + t];
        atomicAdd(&g_z[b * NN + k0 + t], z);
    }

    if (tj != tk) {
        __syncthreads();
        float* sT = sm;
        #pragma unroll
        for (int i = 0; i < 8; i++)
            #pragma unroll
            for (int jj = 0; jj < 4; jj++) {
                sT[(jj * 32 + tx * 2 + 0) * 129 + (ty * 8 + i)] = acc[i][2 * jj + 0];
                sT[(jj * 32 + tx * 2 + 1) * 129 + (ty * 8 + i)] = acc[i][2 * jj + 1];
            }
        __syncthreads();
        int c = t & 127, r0b = t >> 7;
        float zM = 0.f;
        #pragma unroll 4
        for (int p = 0; p < 64; p++) {
            int r = r0b + 2 * p;
            int k = k0 + r, j = j0 + c;
            float am = adjb[(size_t)k * NN + j];
            float ev = am > 0.f ? __expf(sT[r * 129 + c]) : 0.f;
            zM += am > 0.f ? ev : 1.f;
            scb[(size_t)k * NN + j] = packbf(ev);
        }
        atomicAdd(&g_z[b * NN + j0 + c], zM);
    }
}

// ---------------- K4: B' = rz[j] * h[j][d], packed bf16 hi/lo, layout [b][d][j] ----------------
__global__ __launch_bounds__(256) void k_bprep() {
    __shared__ uint32_t sm[32][33];
    int b = blockIdx.z, j0 = blockIdx.x * 32, d0 = blockIdx.y * 32;
    int t = threadIdx.x, c = t & 31, r0 = t >> 5;
    const float* Hb = g_h + (size_t)b * NN * DD;
    const float* zb = g_z + b * NN;
    #pragma unroll
    for (int p = 0; p < 4; p++) {
        int jr = r0 + 8 * p;
        float rz = __fdividef(1.0f, zb[j0 + jr]);
        float v = Hb[(size_t)(j0 + jr) * DD + d0 + c] * rz;
        sm[jr][c] = packbf(v);
    }
    __syncthreads();
    uint32_t* ob = g_hbf + (size_t)b * DD * NN;
    #pragma unroll
    for (int p = 0; p < 4; p++) {
        int dr = r0 + 8 * p;
        ob[(size_t)(d0 + dr) * NN + j0 + c] = sm[c][dr];
    }
}

// ---------------- K5: h_prime = relu( n @ B'^T ) via mma.sync bf16 hi/lo split ----------------
// CTA: 64 i-rows x 128 d-cols, K=1024 in 32 chunks of 32. 8 warps:
// warp w -> rows [(w&3)*16, +16), cols [(w>>2)*64, +64) as 8 n-tiles of 8.
// smem tiles stride 20 u32 (40 halves) -> conflict-free fragment loads.
__global__ __launch_bounds__(256) void k_hprime() {
    __shared__ uint32_t sAhi[64 * 20], sAlo[64 * 20];    //  5120 B each
    __shared__ uint32_t sBhi[128 * 20], sBlo[128 * 20];  // 10240 B each
    int t = threadIdx.x, w = t >> 5, lane = t & 31;
    int gid = lane >> 2, tig = lane & 3;
    int mrow = (w & 3) * 16, ncol = (w >> 2) * 64;
    int b = blockIdx.y, i0 = blockIdx.x * 64;
    const uint32_t* scb = g_scores + (size_t)b * NN * NN;
    const uint32_t* hbf = g_hbf + (size_t)b * DD * NN;

    float acc[8][4];
    #pragma unroll
    for (int nt = 0; nt < 8; nt++)
        #pragma unroll
        for (int q = 0; q < 4; q++) acc[nt][q] = 0.f;

    for (int ch = 0; ch < 32; ch++) {
        int jb = ch * 32;
        // ---- stage A: 64 x 16 uint2 (packed pairs) ----
        #pragma unroll
        for (int p = 0; p < 4; p++) {
            int idx = t + 256 * p;
            int row = idx >> 4, jp = idx & 15;
            uint2 pr = *(const uint2*)&scb[(size_t)(i0 + row) * NN + jb + jp * 2];
            sAhi[row * 20 + jp] = __byte_perm(pr.x, pr.y, 0x5410);
            sAlo[row * 20 + jp] = __byte_perm(pr.x, pr.y, 0x7632);
        }
        // ---- stage B: 128 x 16 uint2 ----
        #pragma unroll
        for (int p = 0; p < 8; p++) {
            int idx = t + 256 * p;
            int row = idx >> 4, jp = idx & 15;
            uint2 pr = *(const uint2*)&hbf[(size_t)row * NN + jb + jp * 2];
            sBhi[row * 20 + jp] = __byte_perm(pr.x, pr.y, 0x5410);
            sBlo[row * 20 + jp] = __byte_perm(pr.x, pr.y, 0x7632);
        }
        __syncthreads();

        #pragma unroll
        for (int s = 0; s < 2; s++) {
            int ab = (mrow + gid) * 20 + s * 8 + tig;
            uint32_t ahi[4], alo[4];
            ahi[0] = sAhi[ab];            ahi[1] = sAhi[ab + 160];
            ahi[2] = sAhi[ab + 4];        ahi[3] = sAhi[ab + 164];
            alo[0] = sAlo[ab];            alo[1] = sAlo[ab + 160];
            alo[2] = sAlo[ab + 4];        alo[3] = sAlo[ab + 164];
            #pragma unroll
            for (int nt = 0; nt < 8; nt++) {
                int bb_ = (ncol + nt * 8 + gid) * 20 + s * 8 + tig;
                uint32_t bhi[2] = { sBhi[bb_], sBhi[bb_ + 4] };
                uint32_t blo[2] = { sBlo[bb_], sBlo[bb_ + 4] };
                mma16816(acc[nt], ahi, bhi);
                mma16816(acc[nt], ahi, blo);
                mma16816(acc[nt], alo, bhi);
            }
        }
        __syncthreads();
    }

    // ---- epilogue: relu + store ----
    float* hpb = g_hp + (size_t)b * NN * DD;
    int r0 = i0 + mrow + gid;
    #pragma unroll
    for (int nt = 0; nt < 8; nt++) {
        int c0 = ncol + nt * 8 + tig * 2;
        float2 v0, v1;
        v0.x = fmaxf(acc[nt][0], 0.f); v0.y = fmaxf(acc[nt][1], 0.f);
        v1.x = fmaxf(acc[nt][2], 0.f); v1.y = fmaxf(acc[nt][3], 0.f);
        *(float2*)&hpb[(size_t)r0 * DD + c0]       = v0;
        *(float2*)&hpb[(size_t)(r0 + 8) * DD + c0] = v1;
    }
}

// ---------------- K6: gates + output ----------------
__global__ __launch_bounds__(256) void k_out(const float* __restrict__ x,
        const float* __restrict__ wi_u, const float* __restrict__ wi_x,
        const float* __restrict__ wf_u, const float* __restrict__ wf_x,
        const float* __restrict__ wo_u, const float* __restrict__ wo_x,
        float* __restrict__ out) {
    int node = blockIdx.x * 8 + (threadIdx.x >> 5);
    int lane = threadIdx.x & 31;
    size_t base = (size_t)node * DD;
    float hp4[4], x4[4];
    float si = 0.f, sf = 0.f, so = 0.f;
    #pragma unroll
    for (int i = 0; i < 4; i++) {
        int d = lane + 32 * i;
        hp4[i] = g_hp[base + d];
        x4[i]  = x[base + d];
        si += hp4[i] * wi_u[d] + x4[i] * wi_x[d];
        sf += hp4[i] * wf_u[d] + x4[i] * wf_x[d];
        so += hp4[i] * wo_u[d] + x4[i] * wo_x[d];
    }
    #pragma unroll
    for (int off = 16; off; off >>= 1) {
        si += __shfl_xor_sync(0xffffffffu, si, off);
        sf += __shfl_xor_sync(0xffffffffu, sf, off);
        so += __shfl_xor_sync(0xffffffffu, so, off);
    }
    float ic = 1.f / (1.f + __expf(-si));
    float fc = 1.f / (1.f + __expf(-sf));
    float oc = 1.f / (1.f + __expf(-so));
    #pragma unroll
    for (int i = 0; i < 4; i++) {
        int d = lane + 32 * i;
        out[base + d] = oc * tanhf(ic * hp4[i] + fc * x4[i]);
    }
}

// ---------------- launch ----------------
extern "C" void kernel_launch(void* const* d_in, const int* in_sizes, int n_in,
                              void* d_out, int out_size) {
    const float* x    = (const float*)d_in[0];
    const float* adj  = (const float*)d_in[1];
    const float* Ww   = (const float*)d_in[2];
    const float* Wb   = (const float*)d_in[3];
    const float* A    = (const float*)d_in[4];
    const float* wi_u = (const float*)d_in[5];
    const float* wi_x = (const float*)d_in[6];
    const float* wf_u = (const float*)d_in[7];
    const float* wf_x = (const float*)d_in[8];
    const float* wo_u = (const float*)d_in[9];
    const float* wo_x = (const float*)d_in[10];
    float* out = (float*)d_out;

    cudaFuncSetAttribute(k_scores, cudaFuncAttributeMaxDynamicSharedMemorySize, SMEM_K3);

    k_prep<<<64, 256>>>(Ww, A);
    k_h_g<<<BN / 64, 256>>>(x, Wb);
    k_scores<<<dim3(36, BB), 256, SMEM_K3>>>(adj);
    k_bprep<<<dim3(NN / 32, DD / 32, BB), 256>>>();
    k_hprime<<<dim3(NN / 64, BB), 256>>>();
    k_out<<<BN / 8, 256>>>(x, wi_u, wi_x, wf_u, wf_x, wo_u, wo_x, out);
}

// round 17
// speedup vs baseline: 1.5302x; 1.2339x over previous
#include <cuda_runtime.h>
#include <cuda_bf16.h>
#include <cstdint>

#define BB 16
#define NN 1024
#define DD 128
#define BN (BB*NN)

// pack float -> (bf16 hi | bf16 lo<<16)
__device__ __forceinline__ uint32_t packbf(float v) {
    __nv_bfloat16 hi = __float2bfloat16(v);
    float lof = v - __bfloat162float(hi);
    __nv_bfloat16 lo = __float2bfloat16(lof);
    return (uint32_t)__bfloat16_as_ushort(hi) | ((uint32_t)__bfloat16_as_ushort(lo) << 16);
}

// mma.sync m16n8k16 row.col f32.bf16.bf16.f32 (arch-generic HMMA)
__device__ __forceinline__ void mma16816(float* d, const uint32_t* a, const uint32_t* b) {
    asm volatile(
        "mma.sync.aligned.m16n8k16.row.col.f32.bf16.bf16.f32 "
        "{%0,%1,%2,%3}, {%4,%5,%6,%7}, {%8,%9}, {%0,%1,%2,%3};"
        : "+f"(d[0]), "+f"(d[1]), "+f"(d[2]), "+f"(d[3])
        : "r"(a[0]), "r"(a[1]), "r"(a[2]), "r"(a[3]), "r"(b[0]), "r"(b[1]));
}

// ---------------- scratch ----------------
__device__ float    g_WwT[DD*DD];
__device__ float    g_M  [DD*DD];               // A + A^T
__device__ float    g_h  [BN*DD];               // fp32 h (for k_bprep)
__device__ uint32_t g_hpk[(size_t)BN*DD];       // h packed bf16 hi/lo, [node][feat]
__device__ uint32_t g_gpk[(size_t)BN*DD];       // g packed bf16 hi/lo, [node][feat]
__device__ uint32_t g_scores[(size_t)BB*NN*NN]; // packed bf16 (hi,lo) numerators
__device__ float    g_z  [BB*NN];
__device__ uint32_t g_hbf[(size_t)BB*DD*NN];    // B' = rz[j]*h[j][d], packed, [b][d][j]
__device__ float    g_hp [BN*DD];

// ---------------- K0: transpose Ww, form M = A+A^T, zero g_z ----------------
__global__ void k_prep(const float* __restrict__ Ww, const float* __restrict__ A) {
    int i = blockIdx.x * 256 + threadIdx.x;
    int d = i >> 7, f = i & 127;
    g_WwT[f * DD + d] = Ww[d * DD + f];
    g_M[d * DD + f] = A[d * DD + f] + A[f * DD + d];
    g_z[i] = 0.f;
}

// ---------------- K1: fused h = x@Ww^T + Wb ; g = h@M (writes packed h,g) ----------------
__global__ __launch_bounds__(256) void k_h_g(const float* __restrict__ x,
                                             const float* __restrict__ Wb) {
    __shared__ float sX[64 * 128];
    int t = threadIdx.x;
    int tx = t & 31, ty = t >> 5;
    int row0 = blockIdx.x * 64;

    #pragma unroll
    for (int i = 0; i < 32; i++) {
        int idx = i * 256 + t;
        sX[idx] = x[(size_t)row0 * DD + idx];
    }
    __syncthreads();

    float acc[8][4];
    float4 wb4 = *(const float4*)&Wb[tx * 4];
    #pragma unroll
    for (int i = 0; i < 8; i++) { acc[i][0]=wb4.x; acc[i][1]=wb4.y; acc[i][2]=wb4.z; acc[i][3]=wb4.w; }
    for (int f = 0; f < 128; f++) {
        float4 w = *(const float4*)&g_WwT[f * DD + tx * 4];
        #pragma unroll
        for (int i = 0; i < 8; i++) {
            float xv = sX[(ty * 8 + i) * 128 + f];
            acc[i][0] += xv * w.x; acc[i][1] += xv * w.y;
            acc[i][2] += xv * w.z; acc[i][3] += xv * w.w;
        }
    }
    __syncthreads();
    #pragma unroll
    for (int i = 0; i < 8; i++) {
        int r = ty * 8 + i;
        float4 v; v.x = acc[i][0]; v.y = acc[i][1]; v.z = acc[i][2]; v.w = acc[i][3];
        *(float4*)&g_h[(size_t)(row0 + r) * DD + tx * 4] = v;
        uint4 pk; pk.x = packbf(v.x); pk.y = packbf(v.y); pk.z = packbf(v.z); pk.w = packbf(v.w);
        *(uint4*)&g_hpk[(size_t)(row0 + r) * DD + tx * 4] = pk;
        *(float4*)&sX[r * 128 + tx * 4] = v;
    }
    __syncthreads();

    float acc2[8][4];
    #pragma unroll
    for (int i = 0; i < 8; i++) { acc2[i][0]=0.f; acc2[i][1]=0.f; acc2[i][2]=0.f; acc2[i][3]=0.f; }
    for (int f = 0; f < 128; f++) {
        float4 m4 = *(const float4*)&g_M[f * DD + tx * 4];
        #pragma unroll
        for (int i = 0; i < 8; i++) {
            float hv = sX[(ty * 8 + i) * 128 + f];
            acc2[i][0] += hv * m4.x; acc2[i][1] += hv * m4.y;
            acc2[i][2] += hv * m4.z; acc2[i][3] += hv * m4.w;
        }
    }
    #pragma unroll
    for (int i = 0; i < 8; i++) {
        uint4 pk;
        pk.x = packbf(acc2[i][0]); pk.y = packbf(acc2[i][1]);
        pk.z = packbf(acc2[i][2]); pk.w = packbf(acc2[i][3]);
        *(uint4*)&g_gpk[(size_t)(row0 + ty * 8 + i) * DD + tx * 4] = pk;
    }
}

// ---------------- K3: e_sym = g @ h^T via mma.sync ; exp+mask+colsum fused ----------------
// 8 warps: warp w -> rows (w&3)*32 (2 m-tiles), cols (w>>2)*64 (8 n-tiles).
// K=128 in 4 chunks of 32. Staging stride 20 u32 (validated conflict-free in k_hprime).
// Epilogue: fragments -> sT[128x129] f32 raw e -> scalar exp/mask/colsum/mirror.
#define SMEM_K3 (128 * 129 * 4)   // 66048 B
__global__ __launch_bounds__(256) void k_scores(const float* __restrict__ adj) {
    extern __shared__ uint32_t smu[];
    uint32_t* sAhi = smu;            // 128*20
    uint32_t* sAlo = smu + 2560;
    uint32_t* sBhi = smu + 5120;
    uint32_t* sBlo = smu + 7680;     // total 40960 B

    int u = blockIdx.x, b = blockIdx.y;
    int tj = 0, rem = u;
    while (rem >= 8 - tj) { rem -= 8 - tj; tj++; }
    int tk = tj + rem;
    int j0 = tj * 128, k0 = tk * 128;

    int t = threadIdx.x, w = t >> 5, lane = t & 31;
    int gid = lane >> 2, tig = lane & 3;
    int mrow = (w & 3) * 32, ncol = (w >> 2) * 64;

    const uint32_t* Gp = g_gpk + (size_t)b * NN * DD;
    const uint32_t* Hp = g_hpk + (size_t)b * NN * DD;

    float acc[2][8][4];
    #pragma unroll
    for (int mt = 0; mt < 2; mt++)
        #pragma unroll
        for (int nt = 0; nt < 8; nt++)
            #pragma unroll
            for (int q = 0; q < 4; q++) acc[mt][nt][q] = 0.f;

    for (int ch = 0; ch < 4; ch++) {
        int f0 = ch * 32;
        #pragma unroll
        for (int p = 0; p < 8; p++) {
            int idx = t + 256 * p;          // 0..2047
            int row = idx >> 4, jp = idx & 15;
            uint2 pa = *(const uint2*)&Gp[(size_t)(j0 + row) * DD + f0 + jp * 2];
            sAhi[row * 20 + jp] = __byte_perm(pa.x, pa.y, 0x5410);
            sAlo[row * 20 + jp] = __byte_perm(pa.x, pa.y, 0x7632);
            uint2 pb = *(const uint2*)&Hp[(size_t)(k0 + row) * DD + f0 + jp * 2];
            sBhi[row * 20 + jp] = __byte_perm(pb.x, pb.y, 0x5410);
            sBlo[row * 20 + jp] = __byte_perm(pb.x, pb.y, 0x7632);
        }
        __syncthreads();
        #pragma unroll
        for (int s = 0; s < 2; s++) {
            #pragma unroll
            for (int mt = 0; mt < 2; mt++) {
                int ab = (mrow + mt * 16 + gid) * 20 + s * 8 + tig;
                uint32_t ahi[4], alo[4];
                ahi[0] = sAhi[ab];       ahi[1] = sAhi[ab + 160];
                ahi[2] = sAhi[ab + 4];   ahi[3] = sAhi[ab + 164];
                alo[0] = sAlo[ab];       alo[1] = sAlo[ab + 160];
                alo[2] = sAlo[ab + 4];   alo[3] = sAlo[ab + 164];
                #pragma unroll
                for (int nt = 0; nt < 8; nt++) {
                    int bb_ = (ncol + nt * 8 + gid) * 20 + s * 8 + tig;
                    uint32_t bhi[2] = { sBhi[bb_], sBhi[bb_ + 4] };
                    uint32_t blo[2] = { sBlo[bb_], sBlo[bb_ + 4] };
                    mma16816(acc[mt][nt], ahi, bhi);
                    mma16816(acc[mt][nt], ahi, blo);
                    mma16816(acc[mt][nt], alo, bhi);
                }
            }
        }
        __syncthreads();
    }

    // ---- fragments -> sT (raw e, natural orientation) ----
    float* sT = (float*)smu;   // 128 x 129 floats = full 66048 B
    #pragma unroll
    for (int mt = 0; mt < 2; mt++)
        #pragma unroll
        for (int nt = 0; nt < 8; nt++) {
            int r = mrow + mt * 16 + gid, c = ncol + nt * 8 + tig * 2;
            sT[r * 129 + c]           = acc[mt][nt][0];
            sT[r * 129 + c + 1]       = acc[mt][nt][1];
            sT[(r + 8) * 129 + c]     = acc[mt][nt][2];
            sT[(r + 8) * 129 + c + 1] = acc[mt][nt][3];
        }
    __syncthreads();

    const float* adjb = adj + (size_t)b * NN * NN;
    uint32_t* scb = g_scores + (size_t)b * NN * NN;
    int tx = t & 15, ty = t >> 4;

    // ---- direct tile: exp + mask + packed write + column partials ----
    float colp[8];
    #pragma unroll
    for (int e = 0; e < 8; e++) colp[e] = 0.f;

    #pragma unroll
    for (int i = 0; i < 8; i++) {
        int jl = ty * 8 + i, j = j0 + jl;
        #pragma unroll
        for (int jj = 0; jj < 4; jj++) {
            int kl = jj * 32 + tx * 2, k = k0 + kl;
            float2 am = *(const float2*)&adjb[(size_t)j * NN + k];
            float vx = am.x > 0.f ? __expf(sT[jl * 129 + kl])     : 0.f;
            float vy = am.y > 0.f ? __expf(sT[jl * 129 + kl + 1]) : 0.f;
            colp[2 * jj + 0] += am.x > 0.f ? vx : 1.f;
            colp[2 * jj + 1] += am.y > 0.f ? vy : 1.f;
            uint2 pk; pk.x = packbf(vx); pk.y = packbf(vy);
            *(uint2*)&scb[(size_t)j * NN + k] = pk;
        }
    }
    // reduce over the two ty's in each warp, then 8-way atomics
    #pragma unroll
    for (int e = 0; e < 8; e++) colp[e] += __shfl_xor_sync(0xffffffffu, colp[e], 16);
    if (lane < 16) {
        #pragma unroll
        for (int jj = 0; jj < 4; jj++) {
            atomicAdd(&g_z[b * NN + k0 + jj * 32 + tx * 2 + 0], colp[2 * jj + 0]);
            atomicAdd(&g_z[b * NN + k0 + jj * 32 + tx * 2 + 1], colp[2 * jj + 1]);
        }
    }

    // ---- mirrored tile ----
    if (tj != tk) {
        int c = t & 127, r0b = t >> 7;
        float zM = 0.f;
        #pragma unroll 4
        for (int p = 0; p < 64; p++) {
            int r = r0b + 2 * p;
            int k = k0 + r, j = j0 + c;
            float am = adjb[(size_t)k * NN + j];
            float ev = am > 0.f ? __expf(sT[c * 129 + r]) : 0.f;
            zM += am > 0.f ? ev : 1.f;
            scb[(size_t)k * NN + j] = packbf(ev);
        }
        atomicAdd(&g_z[b * NN + j0 + c], zM);
    }
}

// ---------------- K4: B' = rz[j] * h[j][d], packed bf16 hi/lo, layout [b][d][j] ----------------
__global__ __launch_bounds__(256) void k_bprep() {
    __shared__ uint32_t sm[32][33];
    int b = blockIdx.z, j0 = blockIdx.x * 32, d0 = blockIdx.y * 32;
    int t = threadIdx.x, c = t & 31, r0 = t >> 5;
    const float* Hb = g_h + (size_t)b * NN * DD;
    const float* zb = g_z + b * NN;
    #pragma unroll
    for (int p = 0; p < 4; p++) {
        int jr = r0 + 8 * p;
        float rz = __fdividef(1.0f, zb[j0 + jr]);
        float v = Hb[(size_t)(j0 + jr) * DD + d0 + c] * rz;
        sm[jr][c] = packbf(v);
    }
    __syncthreads();
    uint32_t* ob = g_hbf + (size_t)b * DD * NN;
    #pragma unroll
    for (int p = 0; p < 4; p++) {
        int dr = r0 + 8 * p;
        ob[(size_t)(d0 + dr) * NN + j0 + c] = sm[c][dr];
    }
}

// ---------------- K5: h_prime = relu( n @ B'^T ) via mma.sync (validated R14) ----------------
__global__ __launch_bounds__(256) void k_hprime() {
    __shared__ uint32_t sAhi[64 * 20], sAlo[64 * 20];
    __shared__ uint32_t sBhi[128 * 20], sBlo[128 * 20];
    int t = threadIdx.x, w = t >> 5, lane = t & 31;
    int gid = lane >> 2, tig = lane & 3;
    int mrow = (w & 3) * 16, ncol = (w >> 2) * 64;
    int b = blockIdx.y, i0 = blockIdx.x * 64;
    const uint32_t* scb = g_scores + (size_t)b * NN * NN;
    const uint32_t* hbf = g_hbf + (size_t)b * DD * NN;

    float acc[8][4];
    #pragma unroll
    for (int nt = 0; nt < 8; nt++)
        #pragma unroll
        for (int q = 0; q < 4; q++) acc[nt][q] = 0.f;

    for (int ch = 0; ch < 32; ch++) {
        int jb = ch * 32;
        #pragma unroll
        for (int p = 0; p < 4; p++) {
            int idx = t + 256 * p;
            int row = idx >> 4, jp = idx & 15;
            uint2 pr = *(const uint2*)&scb[(size_t)(i0 + row) * NN + jb + jp * 2];
            sAhi[row * 20 + jp] = __byte_perm(pr.x, pr.y, 0x5410);
            sAlo[row * 20 + jp] = __byte_perm(pr.x, pr.y, 0x7632);
        }
        #pragma unroll
        for (int p = 0; p < 8; p++) {
            int idx = t + 256 * p;
            int row = idx >> 4, jp = idx & 15;
            uint2 pr = *(const uint2*)&hbf[(size_t)row * NN + jb + jp * 2];
            sBhi[row * 20 + jp] = __byte_perm(pr.x, pr.y, 0x5410);
            sBlo[row * 20 + jp] = __byte_perm(pr.x, pr.y, 0x7632);
        }
        __syncthreads();

        #pragma unroll
        for (int s = 0; s < 2; s++) {
            int ab = (mrow + gid) * 20 + s * 8 + tig;
            uint32_t ahi[4], alo[4];
            ahi[0] = sAhi[ab];            ahi[1] = sAhi[ab + 160];
            ahi[2] = sAhi[ab + 4];        ahi[3] = sAhi[ab + 164];
            alo[0] = sAlo[ab];            alo[1] = sAlo[ab + 160];
            alo[2] = sAlo[ab + 4];        alo[3] = sAlo[ab + 164];
            #pragma unroll
            for (int nt = 0; nt < 8; nt++) {
                int bb_ = (ncol + nt * 8 + gid) * 20 + s * 8 + tig;
                uint32_t bhi[2] = { sBhi[bb_], sBhi[bb_ + 4] };
                uint32_t blo[2] = { sBlo[bb_], sBlo[bb_ + 4] };
                mma16816(acc[nt], ahi, bhi);
                mma16816(acc[nt], ahi, blo);
                mma16816(acc[nt], alo, bhi);
            }
        }
        __syncthreads();
    }

    float* hpb = g_hp + (size_t)b * NN * DD;
    int r0 = i0 + mrow + gid;
    #pragma unroll
    for (int nt = 0; nt < 8; nt++) {
        int c0 = ncol + nt * 8 + tig * 2;
        float2 v0, v1;
        v0.x = fmaxf(acc[nt][0], 0.f); v0.y = fmaxf(acc[nt][1], 0.f);
        v1.x = fmaxf(acc[nt][2], 0.f); v1.y = fmaxf(acc[nt][3], 0.f);
        *(float2*)&hpb[(size_t)r0 * DD + c0]       = v0;
        *(float2*)&hpb[(size_t)(r0 + 8) * DD + c0] = v1;
    }
}

// ---------------- K6: gates + output ----------------
__global__ __launch_bounds__(256) void k_out(const float* __restrict__ x,
        const float* __restrict__ wi_u, const float* __restrict__ wi_x,
        const float* __restrict__ wf_u, const float* __restrict__ wf_x,
        const float* __restrict__ wo_u, const float* __restrict__ wo_x,
        float* __restrict__ out) {
    int node = blockIdx.x * 8 + (threadIdx.x >> 5);
    int lane = threadIdx.x & 31;
    size_t base = (size_t)node * DD;
    float hp4[4], x4[4];
    float si = 0.f, sf = 0.f, so = 0.f;
    #pragma unroll
    for (int i = 0; i < 4; i++) {
        int d = lane + 32 * i;
        hp4[i] = g_hp[base + d];
        x4[i]  = x[base + d];
        si += hp4[i] * wi_u[d] + x4[i] * wi_x[d];
        sf += hp4[i] * wf_u[d] + x4[i] * wf_x[d];
        so += hp4[i] * wo_u[d] + x4[i] * wo_x[d];
    }
    #pragma unroll
    for (int off = 16; off; off >>= 1) {
        si += __shfl_xor_sync(0xffffffffu, si, off);
        sf += __shfl_xor_sync(0xffffffffu, sf, off);
        so += __shfl_xor_sync(0xffffffffu, so, off);
    }
    float ic = 1.f / (1.f + __expf(-si));
    float fc = 1.f / (1.f + __expf(-sf));
    float oc = 1.f / (1.f + __expf(-so));
    #pragma unroll
    for (int i = 0; i < 4; i++) {
        int d = lane + 32 * i;
        out[base + d] = oc * tanhf(ic * hp4[i] + fc * x4[i]);
    }
}

// ---------------- launch ----------------
extern "C" void kernel_launch(void* const* d_in, const int* in_sizes, int n_in,
                              void* d_out, int out_size) {
    const float* x    = (const float*)d_in[0];
    const float* adj  = (const float*)d_in[1];
    const float* Ww   = (const float*)d_in[2];
    const float* Wb   = (const float*)d_in[3];
    const float* A    = (const float*)d_in[4];
    const float* wi_u = (const float*)d_in[5];
    const float* wi_x = (const float*)d_in[6];
    const float* wf_u = (const float*)d_in[7];
    const float* wf_x = (const float*)d_in[8];
    const float* wo_u = (const float*)d_in[9];
    const float* wo_x = (const float*)d_in[10];
    float* out = (float*)d_out;

    cudaFuncSetAttribute(k_scores, cudaFuncAttributeMaxDynamicSharedMemorySize, SMEM_K3);

    k_prep<<<64, 256>>>(Ww, A);
    k_h_g<<<BN / 64, 256>>>(x, Wb);
    k_scores<<<dim3(36, BB), 256, SMEM_K3>>>(adj);
    k_bprep<<<dim3(NN / 32, DD / 32, BB), 256>>>();
    k_hprime<<<dim3(NN / 64, BB), 256>>>();
    k_out<<<BN / 8, 256>>>(x, wi_u, wi_x, wf_u, wf_x, wo_u, wo_x, out);
}